// round 3
// baseline (speedup 1.0000x reference)
#include <cuda_runtime.h>
#include <cuda_bf16.h>

#define TILE 128
#define MAXB 4096

// Scratch (allocation-free rule: __device__ globals).
__device__ double        g_partials[MAXB];
__device__ unsigned int  g_ticket = 0;

__device__ __forceinline__ float pair_loss(float4 q, float P1, float P2, float pi) {
    float t1 = P1 + q.x;                       // 0.2*s - d
    float t2 = P2 + q.y;                       // d - s
    float m  = fmaxf(fmaxf(t1, t2), 0.0f);     // d>=0 branch result (FMNMX3)
    float df = q.z - pi;                       // -d
    return (df > 0.0f) ? df : m;               // d<0 -> |d|
}

__global__ void __launch_bounds__(TILE, 8)
dl_fused_kernel(const float* __restrict__ p,
                const float* __restrict__ z_spacing,
                const float* __restrict__ nth_slice,
                float* __restrict__ out,
                int n, int nblocks) {
    __shared__ float4 qt[TILE];
    __shared__ double wsum[TILE / 32];
    __shared__ bool   is_last;

    const int tid = threadIdx.x;

    // Decode lower-triangular tile pair (bi, bj), bj <= bi, from linear block id.
    int t = blockIdx.x;
    int bi = (int)((sqrtf(8.0f * (float)t + 1.0f) - 1.0f) * 0.5f);
    while ((bi + 1) * (bi + 2) / 2 <= t) bi++;
    while (bi * (bi + 1) / 2 > t) bi--;
    const int bj = t - bi * (bi + 1) / 2;

    const float step = z_spacing[0] * nth_slice[0];   // STEP == 1.0
    const float c02  = 0.2f * step;

    const int gi  = bi * TILE + tid;
    const int gj0 = bj * TILE;
    const int gj  = gj0 + tid;

    // Per-j precompute: q.x = pj - 0.2*step*j ; q.y = step*j - pj ; q.z = pj
    {
        float pv = (gj < n) ? p[gj] : 0.0f;
        float jf = (float)gj;
        qt[tid] = make_float4(pv - c02 * jf, step * jf - pv, pv, 0.0f);
    }

    const bool  i_valid = (gi < n);
    const float pi  = i_valid ? p[gi] : 0.0f;
    const float gif = (float)gi;
    const float P1  = c02 * gif - pi;     // t1 = P1 + q.x
    const float P2  = pi - step * gif;    // t2 = P2 + q.y

    __syncthreads();

    float a0 = 0.0f, a1 = 0.0f, a2 = 0.0f, a3 = 0.0f;
    if (i_valid) {
        if (bi != bj) {
            // Off-diagonal tile: all pairs valid (i - j >= TILE). Branch-free,
            // 4-way unrolled with independent accumulators.
            const int jcnt = min(TILE, n - gj0);
            int jj = 0;
            for (; jj + 4 <= jcnt; jj += 4) {
                float4 q0 = qt[jj + 0];
                float4 q1 = qt[jj + 1];
                float4 q2 = qt[jj + 2];
                float4 q3 = qt[jj + 3];
                a0 += pair_loss(q0, P1, P2, pi);
                a1 += pair_loss(q1, P1, P2, pi);
                a2 += pair_loss(q2, P1, P2, pi);
                a3 += pair_loss(q3, P1, P2, pi);
            }
            for (; jj < jcnt; ++jj)
                a0 += pair_loss(qt[jj], P1, P2, pi);
        } else {
            // Diagonal tile: j <= i only (j == i contributes exactly 0).
            #pragma unroll 4
            for (int jj = 0; jj <= tid; ++jj)
                a0 += pair_loss(qt[jj], P1, P2, pi);
        }
    }

    // Block reduction in double.
    double v = (double)((a0 + a1) + (a2 + a3));
    #pragma unroll
    for (int off = 16; off > 0; off >>= 1)
        v += __shfl_down_sync(0xffffffffu, v, off);
    if ((tid & 31) == 0) wsum[tid >> 5] = v;
    __syncthreads();
    if (tid < 32) {
        v = (tid < (TILE / 32)) ? wsum[tid] : 0.0;
        #pragma unroll
        for (int off = 2; off > 0; off >>= 1)
            v += __shfl_down_sync(0xffffffffu, v, off);
        if (tid == 0) {
            g_partials[blockIdx.x] = v;
            __threadfence();
            unsigned int ticket = atomicAdd(&g_ticket, 1u);
            is_last = (ticket == (unsigned int)(nblocks - 1));
        }
    }
    __syncthreads();

    // Last block: reduce all partials, write output, reset ticket.
    if (is_last) {
        __threadfence();
        double s = 0.0;
        for (int i = tid; i < nblocks; i += TILE)
            s += g_partials[i];
        #pragma unroll
        for (int off = 16; off > 0; off >>= 1)
            s += __shfl_down_sync(0xffffffffu, s, off);
        if ((tid & 31) == 0) wsum[tid >> 5] = s;
        __syncthreads();
        if (tid == 0) {
            double tot = 0.0;
            #pragma unroll
            for (int w = 0; w < TILE / 32; ++w) tot += wsum[w];
            double nn = (double)n * (double)n;
            out[0] = (float)(tot / nn);
            g_ticket = 0;   // reset for next graph replay
        }
    }
}

extern "C" void kernel_launch(void* const* d_in, const int* in_sizes, int n_in,
                              void* d_out, int out_size) {
    const float* p   = (const float*)d_in[0];
    const float* z   = (const float*)d_in[1];
    const float* nth = (const float*)d_in[2];
    float* out = (float*)d_out;
    int n = in_sizes[0];

    int ntiles  = (n + TILE - 1) / TILE;
    int nblocks = ntiles * (ntiles + 1) / 2;
    if (nblocks > MAXB) nblocks = MAXB;  // safety; n=8192 -> 2080

    dl_fused_kernel<<<nblocks, TILE>>>(p, z, nth, out, n, nblocks);
}

// round 4
// speedup vs baseline: 1.1364x; 1.1364x over previous
#include <cuda_runtime.h>
#include <cuda_bf16.h>

#define JT    64     // j-tile width
#define IT    256    // i-tile height (2 rows per thread)
#define NTHR  128
#define MAXB  8192
#define SENT  (-3.0e38f)

__device__ double        g_partials[MAXB];
__device__ unsigned int  g_ticket = 0;

typedef unsigned long long u64;

__device__ __forceinline__ u64 pack2(float lo, float hi) {
    u64 r; asm("mov.b64 %0, {%1, %2};" : "=l"(r) : "f"(lo), "f"(hi)); return r;
}
__device__ __forceinline__ void unpack2(u64 v, float& lo, float& hi) {
    asm("mov.b64 {%0, %1}, %2;" : "=f"(lo), "=f"(hi) : "l"(v));
}
__device__ __forceinline__ u64 add2(u64 a, u64 b) {
    u64 r; asm("add.rn.f32x2 %0, %1, %2;" : "=l"(r) : "l"(a), "l"(b)); return r;
}

// Exact per-pair loss: t1 = 0.2s - d, t2 = d - s, u = -d.
// r = (u > 0) ? u : max(max(t1, t2), 0)  ==  max( (u>0 ? u : max(t1,t2)), 0 )
__device__ __forceinline__ float sel_loss(float t1, float t2, float u) {
    float mm = fmaxf(t1, t2);
    float s  = (u > 0.0f) ? u : mm;
    return fmaxf(s, 0.0f);
}

__global__ void __launch_bounds__(NTHR, 8)
dl_fused_kernel(const float* __restrict__ p,
                const float* __restrict__ z_spacing,
                const float* __restrict__ nth_slice,
                float* __restrict__ out,
                int n, int nblocks) {
    __shared__ float4 qxy[JT / 2];   // (x_{2k}, y_{2k}, x_{2k+1}, y_{2k+1})
    __shared__ float2 qz [JT / 2];   // (pj_{2k}, pj_{2k+1})
    __shared__ double wsum[NTHR / 32];
    __shared__ bool   is_last;

    const int tid = threadIdx.x;

    // Decode (ti, tj): per-ti block count = 4*ti + 4, start(ti) = 2*ti*(ti+1).
    int t  = blockIdx.x;
    int ti = (int)((sqrtf(2.0f * (float)t + 1.0f) - 1.0f) * 0.5f);
    while (2 * (ti + 1) * (ti + 2) <= t) ti++;
    while (2 * ti * (ti + 1) > t) ti--;
    const int tj = t - 2 * ti * (ti + 1);

    const float step = z_spacing[0] * nth_slice[0];   // STEP == 1.0
    const float c02  = 0.2f * step;

    const int gj0 = tj * JT;
    const int gi0 = ti * IT + tid;        // row A
    const int gi1 = gi0 + NTHR;           // row B

    // Stage j-tile: thread tid < 32 handles j = gj0 + 2*tid, +1.
    if (tid < JT / 2) {
        int j0 = gj0 + 2 * tid, j1 = j0 + 1;
        float x0, y0, z0, x1, y1, z1;
        if (j0 < n) {
            float pv = p[j0], jf = (float)j0;
            x0 = pv - c02 * jf; y0 = step * jf - pv; z0 = pv;
        } else { x0 = y0 = z0 = SENT; }
        if (j1 < n) {
            float pv = p[j1], jf = (float)j1;
            x1 = pv - c02 * jf; y1 = step * jf - pv; z1 = pv;
        } else { x1 = y1 = z1 = SENT; }
        qxy[tid] = make_float4(x0, y0, x1, y1);
        qz [tid] = make_float2(z0, z1);
    }

    // Per-row constants.
    const float pi0 = (gi0 < n) ? p[gi0] : 0.0f;
    const float pi1 = (gi1 < n) ? p[gi1] : 0.0f;
    const float gf0 = (float)gi0, gf1 = (float)gi1;
    const u64 P12_0 = pack2(c02 * gf0 - pi0, pi0 - step * gf0);
    const u64 P12_1 = pack2(c02 * gf1 - pi1, pi1 - step * gf1);
    const u64 NPI0  = pack2(-pi0, -pi0);
    const u64 NPI1  = pack2(-pi1, -pi1);

    // rel = gi - gj0: >= JT-1 -> full tile for this row; [0, JT-1) -> partial; <0 -> none.
    int rel0 = (gi0 < n) ? (gi0 - gj0) : -1;
    int rel1 = (gi1 < n) ? (gi1 - gj0) : -1;

    __syncthreads();

    float a0 = 0.0f, a1 = 0.0f, b0 = 0.0f, b1 = 0.0f;

    if (rel0 >= JT - 1 && rel1 >= JT - 1) {
        // Hot path: both rows consume the full j-tile. Packed f32x2 body.
        #pragma unroll 8
        for (int k = 0; k < JT / 2; ++k) {
            float4 xy = qxy[k];
            float2 zz = qz[k];
            u64 xl = pack2(xy.x, xy.y);
            u64 xh = pack2(xy.z, xy.w);
            u64 zp = pack2(zz.x, zz.y);
            {   // row A
                u64 tA = add2(P12_0, xl), tB = add2(P12_0, xh), uu = add2(zp, NPI0);
                float t1, t2, t3, t4, u0, u1;
                unpack2(tA, t1, t2); unpack2(tB, t3, t4); unpack2(uu, u0, u1);
                a0 += sel_loss(t1, t2, u0);
                a1 += sel_loss(t3, t4, u1);
            }
            {   // row B
                u64 tA = add2(P12_1, xl), tB = add2(P12_1, xh), uu = add2(zp, NPI1);
                float t1, t2, t3, t4, u0, u1;
                unpack2(tA, t1, t2); unpack2(tB, t3, t4); unpack2(uu, u0, u1);
                b0 += sel_loss(t1, t2, u0);
                b1 += sel_loss(t3, t4, u1);
            }
        }
    } else {
        // Cold path: per-row handling (full packed / partial scalar / none).
        const float* qxf = (const float*)qxy;
        const float* qzf = (const float*)qz;
        // Row A
        if (rel0 >= JT - 1) {
            #pragma unroll 8
            for (int k = 0; k < JT / 2; ++k) {
                float4 xy = qxy[k];
                float2 zz = qz[k];
                u64 tA = add2(P12_0, pack2(xy.x, xy.y));
                u64 tB = add2(P12_0, pack2(xy.z, xy.w));
                u64 uu = add2(pack2(zz.x, zz.y), NPI0);
                float t1, t2, t3, t4, u0, u1;
                unpack2(tA, t1, t2); unpack2(tB, t3, t4); unpack2(uu, u0, u1);
                a0 += sel_loss(t1, t2, u0);
                a1 += sel_loss(t3, t4, u1);
            }
        } else {
            for (int jj = 0; jj <= rel0; ++jj) {
                int idx = ((jj >> 1) << 2) | ((jj & 1) << 1);
                float t1 = (c02 * gf0 - pi0) + qxf[idx];
                float t2 = (pi0 - step * gf0) + qxf[idx + 1];
                float u  = qzf[jj] - pi0;
                a0 += sel_loss(t1, t2, u);
            }
        }
        // Row B
        if (rel1 >= JT - 1) {
            #pragma unroll 8
            for (int k = 0; k < JT / 2; ++k) {
                float4 xy = qxy[k];
                float2 zz = qz[k];
                u64 tA = add2(P12_1, pack2(xy.x, xy.y));
                u64 tB = add2(P12_1, pack2(xy.z, xy.w));
                u64 uu = add2(pack2(zz.x, zz.y), NPI1);
                float t1, t2, t3, t4, u0, u1;
                unpack2(tA, t1, t2); unpack2(tB, t3, t4); unpack2(uu, u0, u1);
                b0 += sel_loss(t1, t2, u0);
                b1 += sel_loss(t3, t4, u1);
            }
        } else {
            for (int jj = 0; jj <= rel1; ++jj) {
                int idx = ((jj >> 1) << 2) | ((jj & 1) << 1);
                float t1 = (c02 * gf1 - pi1) + qxf[idx];
                float t2 = (pi1 - step * gf1) + qxf[idx + 1];
                float u  = qzf[jj] - pi1;
                b0 += sel_loss(t1, t2, u);
            }
        }
    }

    // Block reduction in double.
    double v = (double)((a0 + a1) + (b0 + b1));
    #pragma unroll
    for (int off = 16; off > 0; off >>= 1)
        v += __shfl_down_sync(0xffffffffu, v, off);
    if ((tid & 31) == 0) wsum[tid >> 5] = v;
    __syncthreads();
    if (tid < 32) {
        v = (tid < (NTHR / 32)) ? wsum[tid] : 0.0;
        #pragma unroll
        for (int off = 2; off > 0; off >>= 1)
            v += __shfl_down_sync(0xffffffffu, v, off);
        if (tid == 0) {
            g_partials[blockIdx.x] = v;
            __threadfence();
            unsigned int ticket = atomicAdd(&g_ticket, 1u);
            is_last = (ticket == (unsigned int)(nblocks - 1));
        }
    }
    __syncthreads();

    // Last block reduces all partials, writes output, resets ticket.
    if (is_last) {
        __threadfence();
        double s = 0.0;
        for (int i = tid; i < nblocks; i += NTHR)
            s += g_partials[i];
        #pragma unroll
        for (int off = 16; off > 0; off >>= 1)
            s += __shfl_down_sync(0xffffffffu, s, off);
        if ((tid & 31) == 0) wsum[tid >> 5] = s;
        __syncthreads();
        if (tid == 0) {
            double tot = 0.0;
            #pragma unroll
            for (int w = 0; w < NTHR / 32; ++w) tot += wsum[w];
            double nn = (double)n * (double)n;
            out[0] = (float)(tot / nn);
            g_ticket = 0;   // reset for next graph replay
        }
    }
}

extern "C" void kernel_launch(void* const* d_in, const int* in_sizes, int n_in,
                              void* d_out, int out_size) {
    const float* p   = (const float*)d_in[0];
    const float* z   = (const float*)d_in[1];
    const float* nth = (const float*)d_in[2];
    float* out = (float*)d_out;
    int n = in_sizes[0];

    int nti = (n + IT - 1) / IT;                 // i-tiles (256 rows each)
    int nblocks = 2 * nti * (nti + 1);           // sum over ti of (4*ti + 4)
    if (nblocks > MAXB) nblocks = MAXB;          // n = 8192 -> 2112

    dl_fused_kernel<<<nblocks, NTHR>>>(p, z, nth, out, n, nblocks);
}